// round 15
// baseline (speedup 1.0000x reference)
#include <cuda_runtime.h>
#include <cuda_fp16.h>

typedef unsigned long long u64;

#define B_MAX 256

__device__ float g_emb[B_MAX * 3 * 32 * 32 * 32];  // [b][c][i][t][j]
__device__ float g_sig[B_MAX * 3 * 32 * 32 * 32];  // y-branch GATE sigmoid(LN(res))
__device__ float g_sg2[B_MAX * 3 * 32 * 32];       // sigmoid(LN(x-branch))

// ---------------- packed f32x2 + misc helpers ----------------
__device__ __forceinline__ u64 pack2(float lo, float hi) {
    u64 r; asm("mov.b64 %0, {%1, %2};" : "=l"(r) : "f"(lo), "f"(hi)); return r;
}
__device__ __forceinline__ void unpack2(u64 v, float& lo, float& hi) {
    asm("mov.b64 {%0, %1}, %2;" : "=f"(lo), "=f"(hi) : "l"(v));
}
__device__ __forceinline__ u64 fma2(u64 a, u64 b, u64 c) {
    u64 d; asm("fma.rn.f32x2 %0, %1, %2, %3;" : "=l"(d) : "l"(a), "l"(b), "l"(c)); return d;
}
__device__ __forceinline__ u64 mul2(u64 a, u64 b) {
    u64 d; asm("mul.rn.f32x2 %0, %1, %2;" : "=l"(d) : "l"(a), "l"(b)); return d;
}
__device__ __forceinline__ u64 f2u(float2 v) {
    u64 r; asm("mov.b64 %0, {%1, %2};" : "=l"(r) : "f"(v.x), "f"(v.y)); return r;
}
__device__ __forceinline__ unsigned h2u(__half2 h) { return *(unsigned*)&h; }
__device__ __forceinline__ float2 u2f2(unsigned u) { __half2 h = *(__half2*)&u; return __half22float2(h); }
__device__ __forceinline__ float ex2_(float x) {
    float r; asm("ex2.approx.f32 %0, %1;" : "=f"(r) : "f"(x)); return r;
}
__device__ __forceinline__ float sigmoid_(float v) { return 1.0f / (1.0f + __expf(-v)); }
__device__ __forceinline__ unsigned tf32_(float x) {
    unsigned u; asm("cvt.rna.tf32.f32 %0, %1;" : "=r"(u) : "f"(x)); return u;
}
__device__ __forceinline__ void mma_(float c[4], const unsigned a[4], const unsigned b[2]) {
    asm volatile(
        "mma.sync.aligned.m16n8k8.row.col.f32.tf32.tf32.f32 "
        "{%0,%1,%2,%3}, {%4,%5,%6,%7}, {%8,%9}, {%0,%1,%2,%3};"
        : "+f"(c[0]), "+f"(c[1]), "+f"(c[2]), "+f"(c[3])
        : "r"(a[0]), "r"(a[1]), "r"(a[2]), "r"(a[3]), "r"(b[0]), "r"(b[1]));
}

// bank-conflict-free strides (verified R10):
#define ST 37     // st/qbuf row stride
#define WS 104    // sWt row stride (8 mod 32)
#define W0S 40    // sW0t row stride (8 mod 32)
#define KVS 36    // kv token stride in 32-bit words

// ---------------------------------------------------------------------------
// K1 v2 (unchanged, verified)
// ---------------------------------------------------------------------------
__global__ void __launch_bounds__(256) k_emb2(const float* __restrict__ x,
                                              const float* __restrict__ pos)
{
    __shared__ float ps[32 * 36];
    __shared__ float xs[2][32 * 33];

    int bc = blockIdx.x;
    int c = bc % 3;
    int tid = threadIdx.x;

    {
        float4 pv = ((const float4*)(pos + c * 1024))[tid];
        int j = tid >> 3, d0 = (tid & 7) * 4;
        ps[(d0 + 0) * 36 + j] = pv.x;
        ps[(d0 + 1) * 36 + j] = pv.y;
        ps[(d0 + 2) * 36 + j] = pv.z;
        ps[(d0 + 3) * 36 + j] = pv.w;
    }

    const float* xb = x + (size_t)bc * 32768;
    float* ob = g_emb + (size_t)bc * 32768;
    int i  = tid >> 3, j0 = (tid & 7) * 4;
    int dd = tid >> 3, i4 = (tid & 7) * 4;

    for (int tg = 0; tg < 16; tg++) {
        float4 xv0 = ((const float4*)(xb + (size_t)(2 * tg)     * 1024))[tid];
        float4 xv1 = ((const float4*)(xb + (size_t)(2 * tg + 1) * 1024))[tid];
        __syncthreads();
        xs[0][dd * 33 + i4 + 0] = xv0.x; xs[0][dd * 33 + i4 + 1] = xv0.y;
        xs[0][dd * 33 + i4 + 2] = xv0.z; xs[0][dd * 33 + i4 + 3] = xv0.w;
        xs[1][dd * 33 + i4 + 0] = xv1.x; xs[1][dd * 33 + i4 + 1] = xv1.y;
        xs[1][dd * 33 + i4 + 2] = xv1.z; xs[1][dd * 33 + i4 + 3] = xv1.w;
        __syncthreads();

        u64 a00 = 0, a01 = 0, a10 = 0, a11 = 0;
#pragma unroll
        for (int d = 0; d < 32; d++) {
            ulonglong2 p = *(const ulonglong2*)(ps + d * 36 + j0);
            float x0 = xs[0][d * 33 + i];
            float x1 = xs[1][d * 33 + i];
            u64 x0p = pack2(x0, x0), x1p = pack2(x1, x1);
            a00 = fma2(x0p, p.x, a00); a01 = fma2(x0p, p.y, a01);
            a10 = fma2(x1p, p.x, a10); a11 = fma2(x1p, p.y, a11);
        }
        float b0, b1, b2, b3;
        unpack2(a00, b0, b1); unpack2(a01, b2, b3);
        *(float4*)(ob + (size_t)i * 1024 + (2 * tg) * 32 + j0) = make_float4(b0, b1, b2, b3);
        unpack2(a10, b0, b1); unpack2(a11, b2, b3);
        *(float4*)(ob + (size_t)i * 1024 + (2 * tg + 1) * 32 + j0) = make_float4(b0, b1, b2, b3);
    }
}

// ---------------------------------------------------------------------------
// K3 v7b: R10's verified tensor-core kernel + fused LN/sigmoid epilogue.
// Writes the GATE (sigmoid(LN(E + proj))) to g_sig.
// ---------------------------------------------------------------------------
__global__ void __launch_bounds__(128) k_attn_y7b(
    const float* __restrict__ Wqvk, const float* __restrict__ W0,
    const float* __restrict__ gam, const float* __restrict__ bet, int base)
{
    extern __shared__ float sm[];
    unsigned* sWt  = (unsigned*)sm;                 // 32*WS
    unsigned* sW0t = (unsigned*)sm + 32 * WS;       // 32*W0S
    float*    sgb  = sm + 32 * WS + 32 * W0S;       // 64 (gamma|beta)

    const int WB = 32 * WS + 32 * W0S + 64;
    const int PW = 2 * 32 * ST + 32 * KVS;          // per-warp floats

    int tid = threadIdx.x;
    int w = tid >> 5, lane = tid & 31;
    float* st   = sm + WB + w * PW;
    float* qbuf = st + 32 * ST;
    unsigned* kvw = (unsigned*)(qbuf + 32 * ST);

    int cid = base + blockIdx.x;
    int bc = cid >> 3;
    int ib = cid & 7;
    int c = bc % 3;

    // stage transposed tf32 weights + gamma/beta (once per CTA)
    for (int k = tid; k < 3072; k += 128) {
        int f = k >> 5, j = k & 31;
        sWt[j * WS + f] = tf32_(Wqvk[c * 3072 + k]);
    }
    for (int k = tid; k < 1024; k += 128) {
        int jo = k >> 5, ji = k & 31;
        sW0t[ji * W0S + jo] = tf32_(W0[c * 1024 + k]);
    }
    if (tid < 32) { sgb[tid] = gam[tid]; sgb[32 + tid] = bet[tid]; }
    __syncthreads();

    int i = ib * 4 + w;
    const float* eg = g_emb + ((size_t)bc * 32 + i) * 1024;
    float* og       = g_sig + ((size_t)bc * 32 + i) * 1024;

    int gid = lane >> 2;
    int tig = lane & 3;

    // ---- stage E coalesced -> stride-ST ----
#pragma unroll
    for (int r = 0; r < 32; r++) st[r * ST + lane] = eg[r * 32 + lane];
    __syncwarp();

    // ---- A fragments of E ----
    unsigned aq[2][4][4];
#pragma unroll
    for (int m = 0; m < 2; m++)
#pragma unroll
        for (int kk = 0; kk < 4; kk++) {
            int r = m * 16 + gid, cc = kk * 8 + tig;
            aq[m][kk][0] = tf32_(st[r * ST + cc]);
            aq[m][kk][1] = tf32_(st[(r + 8) * ST + cc]);
            aq[m][kk][2] = tf32_(st[r * ST + cc + 4]);
            aq[m][kk][3] = tf32_(st[(r + 8) * ST + cc + 4]);
        }

    const float QS = 0.72134752044f;   // 0.5 * log2(e)

    // ---- QKV GEMM, d-pair major; q -> qbuf, KV -> packed half2 words ----
#pragma unroll
    for (int dp = 0; dp < 2; dp++) {
        float cck[2][2][4], ccv[2][2][4];   // [dd][m][reg]
#pragma unroll
        for (int dd = 0; dd < 2; dd++) {
            int d = 2 * dp + dd;
#pragma unroll
            for (int wh = 0; wh < 3; wh++) {
                int n = 3 * d + wh;     // n-tile: f = d*24 + wh*8 + h
                unsigned b[4][2];
#pragma unroll
                for (int kk = 0; kk < 4; kk++) {
                    b[kk][0] = sWt[(kk * 8 + tig) * WS + n * 8 + gid];
                    b[kk][1] = sWt[(kk * 8 + tig + 4) * WS + n * 8 + gid];
                }
#pragma unroll
                for (int m = 0; m < 2; m++) {
                    float cc[4] = {0.f, 0.f, 0.f, 0.f};
#pragma unroll
                    for (int kk = 0; kk < 4; kk++) mma_(cc, aq[m][kk], b[kk]);
                    if (wh == 0) {
                        int t = m * 16 + gid, h = 2 * tig;
                        qbuf[t * ST + h * 4 + d]             = cc[0] * QS;
                        qbuf[t * ST + (h + 1) * 4 + d]       = cc[1] * QS;
                        qbuf[(t + 8) * ST + h * 4 + d]       = cc[2] * QS;
                        qbuf[(t + 8) * ST + (h + 1) * 4 + d] = cc[3] * QS;
                    } else if (wh == 1) {
#pragma unroll
                        for (int r2 = 0; r2 < 4; r2++) cck[dd][m][r2] = cc[r2];
                    } else {
#pragma unroll
                        for (int r2 = 0; r2 < 4; r2++) ccv[dd][m][r2] = cc[r2];
                    }
                }
            }
        }
        // pack (d, d+1) half2 and store words: kv slot (t,h) = [k01,k23,v01,v23]
#pragma unroll
        for (int m = 0; m < 2; m++)
#pragma unroll
            for (int rh = 0; rh < 2; rh++)
#pragma unroll
                for (int p = 0; p < 2; p++) {
                    int reg = p + 2 * rh;
                    int t = m * 16 + rh * 8 + gid;
                    int h = 2 * tig + p;
                    unsigned kw = h2u(__floats2half2_rn(cck[0][m][reg], cck[1][m][reg]));
                    unsigned vw = h2u(__floats2half2_rn(ccv[0][m][reg], ccv[1][m][reg]));
                    kvw[t * KVS + 4 * h + dp]     = kw;
                    kvw[t * KVS + 4 * h + 2 + dp] = vw;
                }
    }
    __syncwarp();

    // ---- per-head softmax(exp2) + AV; o overwrites q slot in qbuf ----
#pragma unroll 1
    for (int h = 0; h < 8; h++) {
        float q0 = qbuf[lane * ST + 4 * h + 0];
        float q1 = qbuf[lane * ST + 4 * h + 1];
        float q2 = qbuf[lane * ST + 4 * h + 2];
        float q3 = qbuf[lane * ST + 4 * h + 3];
        u64 q01 = pack2(q0, q1), q23 = pack2(q2, q3);

        float sum = 0.f;
        u64 a01 = 0, a23 = 0;
#pragma unroll 8
        for (int s = 0; s < 32; s++) {
            uint4 u = *(uint4*)(kvw + s * KVS + 4 * h);   // uniform broadcast
            u64 t = fma2(q23, f2u(u2f2(u.y)), mul2(q01, f2u(u2f2(u.x))));
            float ta, tb; unpack2(t, ta, tb);
            float p = ex2_(ta + tb);
            sum += p;
            u64 p2 = pack2(p, p);
            a01 = fma2(p2, f2u(u2f2(u.z)), a01);
            a23 = fma2(p2, f2u(u2f2(u.w)), a23);
        }
        float inv = 1.f / sum;
        float oa, ob, oc, od;
        unpack2(a01, oa, ob); unpack2(a23, oc, od);
        qbuf[lane * ST + 4 * h + 0] = oa * inv;
        qbuf[lane * ST + 4 * h + 1] = ob * inv;
        qbuf[lane * ST + 4 * h + 2] = oc * inv;
        qbuf[lane * ST + 4 * h + 3] = od * inv;
    }
    __syncwarp();   // o matrix complete before cross-lane fragment reads

    // ---- W0 GEMM + residual (in-place into st) ----
    unsigned ao[2][4][4];
#pragma unroll
    for (int m = 0; m < 2; m++)
#pragma unroll
        for (int kk = 0; kk < 4; kk++) {
            int r = m * 16 + gid, cc = kk * 8 + tig;
            ao[m][kk][0] = tf32_(qbuf[r * ST + cc]);
            ao[m][kk][1] = tf32_(qbuf[(r + 8) * ST + cc]);
            ao[m][kk][2] = tf32_(qbuf[r * ST + cc + 4]);
            ao[m][kk][3] = tf32_(qbuf[(r + 8) * ST + cc + 4]);
        }

#pragma unroll
    for (int n = 0; n < 4; n++) {
        unsigned b[4][2];
#pragma unroll
        for (int kk = 0; kk < 4; kk++) {
            b[kk][0] = sW0t[(kk * 8 + tig) * W0S + n * 8 + gid];
            b[kk][1] = sW0t[(kk * 8 + tig + 4) * W0S + n * 8 + gid];
        }
#pragma unroll
        for (int m = 0; m < 2; m++) {
            float cc[4] = {0.f, 0.f, 0.f, 0.f};
#pragma unroll
            for (int kk = 0; kk < 4; kk++) mma_(cc, ao[m][kk], b[kk]);
            int t = m * 16 + gid;
            int f0 = n * 8 + 2 * tig;
            st[t * ST + f0]           += cc[0];
            st[t * ST + f0 + 1]       += cc[1];
            st[(t + 8) * ST + f0]     += cc[2];
            st[(t + 8) * ST + f0 + 1] += cc[3];
        }
    }
    __syncwarp();

    // ---- fused LN + sigmoid: lane owns row `lane` (conflict-free stride ST) ----
    {
        float s1 = 0.f, s2 = 0.f;
#pragma unroll
        for (int j = 0; j < 32; j++) {
            float v = st[lane * ST + j];
            s1 += v;
            s2 = fmaf(v, v, s2);
        }
        float mu = s1 * 0.03125f;
        float var = fmaf(-mu, mu, s2 * 0.03125f);
        float rstd = rsqrtf(var + 1e-5f);
#pragma unroll
        for (int j = 0; j < 32; j++) {
            float v = st[lane * ST + j];
            st[lane * ST + j] = sigmoid_((v - mu) * rstd * sgb[j] + sgb[32 + j]);
        }
    }
    __syncwarp();

    // ---- coalesced store of gate ----
#pragma unroll
    for (int r = 0; r < 32; r++) og[r * 32 + lane] = st[r * ST + lane];
}

// ---------------------------------------------------------------------------
// x-branch full warp attention (unchanged, fp32)
// ---------------------------------------------------------------------------
__device__ __forceinline__ void warp_attn_full(
    int lane,
    const float* __restrict__ eg, float* __restrict__ og,
    const float* __restrict__ sW, const float* __restrict__ sW0,
    const float* __restrict__ sgb, float* __restrict__ skv)
{
    u64 e2[16];
    {
        const ulonglong2* ep = (const ulonglong2*)(eg + lane * 32);
#pragma unroll
        for (int j = 0; j < 8; j++) { ulonglong2 v = ep[j]; e2[2*j] = v.x; e2[2*j+1] = v.y; }
    }
    float rr[32];
#pragma unroll
    for (int j = 0; j < 16; j++) unpack2(e2[j], rr[2*j], rr[2*j+1]);

#pragma unroll 1
    for (int h = 0; h < 8; h++) {
        float q[4], kk[4], vv[4];
#pragma unroll
        for (int d = 0; d < 4; d++) {
            const ulonglong2* wq = (const ulonglong2*)(sW + (d * 24 + h)      * 32);
            const ulonglong2* wk = (const ulonglong2*)(sW + (d * 24 + 8 + h)  * 32);
            const ulonglong2* wv = (const ulonglong2*)(sW + (d * 24 + 16 + h) * 32);
            u64 aq = 0, ak = 0, av = 0;
#pragma unroll
            for (int j = 0; j < 8; j++) {
                ulonglong2 ww;
                ww = wq[j]; aq = fma2(e2[2*j+1], ww.y, fma2(e2[2*j], ww.x, aq));
                ww = wk[j]; ak = fma2(e2[2*j+1], ww.y, fma2(e2[2*j], ww.x, ak));
                ww = wv[j]; av = fma2(e2[2*j+1], ww.y, fma2(e2[2*j], ww.x, av));
            }
            float a, b;
            unpack2(aq, a, b); q[d]  = (a + b) * 0.5f;
            unpack2(ak, a, b); kk[d] = a + b;
            unpack2(av, a, b); vv[d] = a + b;
        }
        *(float4*)(skv + lane * 12)     = make_float4(kk[0], kk[1], kk[2], kk[3]);
        *(float4*)(skv + lane * 12 + 4) = make_float4(vv[0], vv[1], vv[2], vv[3]);
        u64 q01 = pack2(q[0], q[1]), q23 = pack2(q[2], q[3]);
        __syncwarp();

        float sum = 0.f;
        u64 a01 = 0, a23 = 0;
#pragma unroll
        for (int s = 0; s < 32; s++) {
            ulonglong2 k2 = *(const ulonglong2*)(skv + s * 12);
            ulonglong2 v2 = *(const ulonglong2*)(skv + s * 12 + 4);
            u64 t = fma2(q23, k2.y, mul2(q01, k2.x));
            float ta, tb; unpack2(t, ta, tb);
            float p = __expf(ta + tb);
            sum += p;
            u64 p2 = pack2(p, p);
            a01 = fma2(p2, v2.x, a01);
            a23 = fma2(p2, v2.y, a23);
        }
        __syncwarp();
        float inv = 1.f / sum;
        float oa, ob, oc, od;
        unpack2(a01, oa, ob); unpack2(a23, oc, od);
        u64 o01 = pack2(oa * inv, ob * inv), o23 = pack2(oc * inv, od * inv);

        const float* w0h = sW0 + 4 * h;
#pragma unroll
        for (int j = 0; j < 32; j += 2) {
            ulonglong2 wa = *(const ulonglong2*)(w0h + j * 32);
            ulonglong2 wb = *(const ulonglong2*)(w0h + (j + 1) * 32);
            u64 ra = fma2(o23, wa.y, mul2(o01, wa.x));
            u64 rb = fma2(o23, wb.y, mul2(o01, wb.x));
            float xa, xb;
            unpack2(ra, xa, xb); rr[j]     += xa + xb;
            unpack2(rb, xa, xb); rr[j + 1] += xa + xb;
        }
    }

    float s1 = 0.f;
#pragma unroll
    for (int j = 0; j < 32; j++) s1 += rr[j];
    float mu = s1 * 0.03125f;
    float sq = 0.f;
#pragma unroll
    for (int j = 0; j < 32; j++) { float d = rr[j] - mu; sq = fmaf(d, d, sq); }
    float rstd = rsqrtf(sq * 0.03125f + 1e-5f);

    float* po = og + lane * 32;
#pragma unroll
    for (int j = 0; j < 32; j += 4) {
        float4 v;
        v.x = sigmoid_((rr[j]     - mu) * rstd * sgb[j]     + sgb[32 + j]);
        v.y = sigmoid_((rr[j + 1] - mu) * rstd * sgb[j + 1] + sgb[33 + j]);
        v.z = sigmoid_((rr[j + 2] - mu) * rstd * sgb[j + 2] + sgb[34 + j]);
        v.w = sigmoid_((rr[j + 3] - mu) * rstd * sgb[j + 3] + sgb[35 + j]);
        *(float4*)(po + j) = v;
    }
}

__global__ void __launch_bounds__(128) k_attn_x2(
    const float* __restrict__ Wqvk, const float* __restrict__ W0,
    const float* __restrict__ g, const float* __restrict__ b, int nb4)
{
    __shared__ float sW[3072];
    __shared__ float sW0[1024];
    __shared__ float sgb[64];
    __shared__ float tiles[4 * 384];

    int tid = threadIdx.x;
    int w = tid >> 5, lane = tid & 31;
    int c  = blockIdx.x / nb4;
    int bq = blockIdx.x % nb4;

    for (int k = tid; k < 768; k += 128) ((float4*)sW)[k]  = ((const float4*)(Wqvk + c * 3072))[k];
    for (int k = tid; k < 256; k += 128) ((float4*)sW0)[k] = ((const float4*)(W0 + c * 1024))[k];
    if (tid < 32) { sgb[tid] = g[tid]; sgb[32 + tid] = b[tid]; }
    __syncthreads();

    int bb = bq * 4 + w;
    const float* eg = g_emb + (((size_t)bb * 3 + 2) * 32 + 31) * 1024;
    float* og = g_sg2 + ((size_t)bb * 3 + c) * 1024;
    warp_attn_full(lane, eg, og, sW, sW0, sgb, tiles + w * 384);
}

// ---------------------------------------------------------------------------
// K4 light (verified R2 form, 44.4us): out = sg2 * gate * x
// ---------------------------------------------------------------------------
__global__ void __launch_bounds__(256) k_final(const float* __restrict__ x,
                                               float* __restrict__ out)
{
    __shared__ float gs[32 * 33]; // gs[i][j]
    __shared__ float ss[32];
    int bct = blockIdx.x;
    int t = bct & 31;
    int bc = bct >> 5;
    int tid = threadIdx.x;

    int i = tid >> 3, j0 = (tid & 7) * 4;
    float4 gv = *(const float4*)(g_sig + ((size_t)bc * 32 + i) * 1024 + t * 32 + j0);
    gs[i * 33 + j0 + 0] = gv.x; gs[i * 33 + j0 + 1] = gv.y;
    gs[i * 33 + j0 + 2] = gv.z; gs[i * 33 + j0 + 3] = gv.w;
    if (tid < 32) ss[tid] = g_sg2[(size_t)bc * 1024 + tid * 32 + t];
    __syncthreads();

    float4 xv = ((const float4*)(x + (size_t)bct * 1024))[tid];
    int jj = tid >> 3, i0 = (tid & 7) * 4;
    float4 ov;
    ov.x = ss[i0 + 0] * gs[(i0 + 0) * 33 + jj] * xv.x;
    ov.y = ss[i0 + 1] * gs[(i0 + 1) * 33 + jj] * xv.y;
    ov.z = ss[i0 + 2] * gs[(i0 + 2) * 33 + jj] * xv.z;
    ov.w = ss[i0 + 3] * gs[(i0 + 3) * 33 + jj] * xv.w;
    ((float4*)(out + (size_t)bct * 1024))[tid] = ov;
}

// ---------------------------------------------------------------------------
extern "C" void kernel_launch(void* const* d_in, const int* in_sizes, int n_in,
                              void* d_out, int out_size)
{
    const float* x   = (const float*)d_in[0];
    const float* pos = (const float*)d_in[1];
    const float* Wqy = (const float*)d_in[2];
    const float* W0y = (const float*)d_in[3];
    const float* gy  = (const float*)d_in[4];
    const float* by  = (const float*)d_in[5];
    const float* Wqx = (const float*)d_in[6];
    const float* W0x = (const float*)d_in[7];
    const float* gx  = (const float*)d_in[8];
    const float* bx  = (const float*)d_in[9];
    float* out = (float*)d_out;

    int B = in_sizes[0] / 98304;  // 3*32*32*32

    const int SMEM_Y = (32 * WS + 32 * W0S + 64 + 4 * (2 * 32 * ST + 32 * KVS)) * 4;  // 75,008 B
    cudaFuncSetAttribute(k_attn_y7b, cudaFuncAttributeMaxDynamicSharedMemorySize, SMEM_Y);

    int nY = B * 24;
    int h1 = nY / 2;
    int nb4 = B / 4;

    k_emb2<<<B * 3, 256>>>(x, pos);
    k_attn_x2<<<3 * nb4, 128>>>(Wqx, W0x, gx, bx, nb4);
    k_attn_y7b<<<h1, 128, SMEM_Y>>>(Wqy, W0y, gy, by, 0);
    k_attn_y7b<<<nY - h1, 128, SMEM_Y>>>(Wqy, W0y, gy, by, h1);
    k_final<<<B * 96, 256>>>(x, out);
}

// round 16
// speedup vs baseline: 1.1072x; 1.1072x over previous
#include <cuda_runtime.h>
#include <cuda_fp16.h>

typedef unsigned long long u64;

#define B_MAX 256

__device__ float g_emb[B_MAX * 3 * 32 * 32 * 32];  // [b][c][i][t][j]
__device__ float g_sig[B_MAX * 3 * 32 * 32 * 32];  // y-branch residual (emb + proj)
__device__ float g_sg2[B_MAX * 3 * 32 * 32];       // sigmoid(LN(x-branch))

// ---------------- packed f32x2 + misc helpers ----------------
__device__ __forceinline__ u64 pack2(float lo, float hi) {
    u64 r; asm("mov.b64 %0, {%1, %2};" : "=l"(r) : "f"(lo), "f"(hi)); return r;
}
__device__ __forceinline__ void unpack2(u64 v, float& lo, float& hi) {
    asm("mov.b64 {%0, %1}, %2;" : "=f"(lo), "=f"(hi) : "l"(v));
}
__device__ __forceinline__ u64 fma2(u64 a, u64 b, u64 c) {
    u64 d; asm("fma.rn.f32x2 %0, %1, %2, %3;" : "=l"(d) : "l"(a), "l"(b), "l"(c)); return d;
}
__device__ __forceinline__ u64 mul2(u64 a, u64 b) {
    u64 d; asm("mul.rn.f32x2 %0, %1, %2;" : "=l"(d) : "l"(a), "l"(b)); return d;
}
__device__ __forceinline__ u64 f2u(float2 v) {
    u64 r; asm("mov.b64 %0, {%1, %2};" : "=l"(r) : "f"(v.x), "f"(v.y)); return r;
}
__device__ __forceinline__ unsigned h2u(__half2 h) { return *(unsigned*)&h; }
__device__ __forceinline__ float2 u2f2(unsigned u) { __half2 h = *(__half2*)&u; return __half22float2(h); }
__device__ __forceinline__ float ex2_(float x) {
    float r; asm("ex2.approx.f32 %0, %1;" : "=f"(r) : "f"(x)); return r;
}
__device__ __forceinline__ float sigmoid_(float v) { return 1.0f / (1.0f + __expf(-v)); }
__device__ __forceinline__ unsigned tf32_(float x) {
    unsigned u; asm("cvt.rna.tf32.f32 %0, %1;" : "=r"(u) : "f"(x)); return u;
}
__device__ __forceinline__ void mma_(float c[4], const unsigned a[4], const unsigned b[2]) {
    asm volatile(
        "mma.sync.aligned.m16n8k8.row.col.f32.tf32.tf32.f32 "
        "{%0,%1,%2,%3}, {%4,%5,%6,%7}, {%8,%9}, {%0,%1,%2,%3};"
        : "+f"(c[0]), "+f"(c[1]), "+f"(c[2]), "+f"(c[3])
        : "r"(a[0]), "r"(a[1]), "r"(a[2]), "r"(a[3]), "r"(b[0]), "r"(b[1]));
}

// bank-conflict-free strides (verified R10):
#define ST 37     // st/qbuf row stride
#define WS 104    // sWt row stride (8 mod 32)
#define W0S 40    // sW0t row stride (8 mod 32)
#define KVS 36    // kv token stride in 32-bit words

// ---------------------------------------------------------------------------
// K1 v2 (unchanged, verified)
// ---------------------------------------------------------------------------
__global__ void __launch_bounds__(256) k_emb2(const float* __restrict__ x,
                                              const float* __restrict__ pos)
{
    __shared__ float ps[32 * 36];
    __shared__ float xs[2][32 * 33];

    int bc = blockIdx.x;
    int c = bc % 3;
    int tid = threadIdx.x;

    {
        float4 pv = ((const float4*)(pos + c * 1024))[tid];
        int j = tid >> 3, d0 = (tid & 7) * 4;
        ps[(d0 + 0) * 36 + j] = pv.x;
        ps[(d0 + 1) * 36 + j] = pv.y;
        ps[(d0 + 2) * 36 + j] = pv.z;
        ps[(d0 + 3) * 36 + j] = pv.w;
    }

    const float* xb = x + (size_t)bc * 32768;
    float* ob = g_emb + (size_t)bc * 32768;
    int i  = tid >> 3, j0 = (tid & 7) * 4;
    int dd = tid >> 3, i4 = (tid & 7) * 4;

    for (int tg = 0; tg < 16; tg++) {
        float4 xv0 = ((const float4*)(xb + (size_t)(2 * tg)     * 1024))[tid];
        float4 xv1 = ((const float4*)(xb + (size_t)(2 * tg + 1) * 1024))[tid];
        __syncthreads();
        xs[0][dd * 33 + i4 + 0] = xv0.x; xs[0][dd * 33 + i4 + 1] = xv0.y;
        xs[0][dd * 33 + i4 + 2] = xv0.z; xs[0][dd * 33 + i4 + 3] = xv0.w;
        xs[1][dd * 33 + i4 + 0] = xv1.x; xs[1][dd * 33 + i4 + 1] = xv1.y;
        xs[1][dd * 33 + i4 + 2] = xv1.z; xs[1][dd * 33 + i4 + 3] = xv1.w;
        __syncthreads();

        u64 a00 = 0, a01 = 0, a10 = 0, a11 = 0;
#pragma unroll
        for (int d = 0; d < 32; d++) {
            ulonglong2 p = *(const ulonglong2*)(ps + d * 36 + j0);
            float x0 = xs[0][d * 33 + i];
            float x1 = xs[1][d * 33 + i];
            u64 x0p = pack2(x0, x0), x1p = pack2(x1, x1);
            a00 = fma2(x0p, p.x, a00); a01 = fma2(x0p, p.y, a01);
            a10 = fma2(x1p, p.x, a10); a11 = fma2(x1p, p.y, a11);
        }
        float b0, b1, b2, b3;
        unpack2(a00, b0, b1); unpack2(a01, b2, b3);
        *(float4*)(ob + (size_t)i * 1024 + (2 * tg) * 32 + j0) = make_float4(b0, b1, b2, b3);
        unpack2(a10, b0, b1); unpack2(a11, b2, b3);
        *(float4*)(ob + (size_t)i * 1024 + (2 * tg + 1) * 32 + j0) = make_float4(b0, b1, b2, b3);
    }
}

// ---------------------------------------------------------------------------
// x-branch full warp attention (verified, fp32)
// ---------------------------------------------------------------------------
__device__ __forceinline__ void warp_attn_full(
    int lane,
    const float* __restrict__ eg, float* __restrict__ og,
    const float* __restrict__ sW, const float* __restrict__ sW0,
    const float* __restrict__ sgb, float* __restrict__ skv)
{
    u64 e2[16];
    {
        const ulonglong2* ep = (const ulonglong2*)(eg + lane * 32);
#pragma unroll
        for (int j = 0; j < 8; j++) { ulonglong2 v = ep[j]; e2[2*j] = v.x; e2[2*j+1] = v.y; }
    }
    float rr[32];
#pragma unroll
    for (int j = 0; j < 16; j++) unpack2(e2[j], rr[2*j], rr[2*j+1]);

#pragma unroll 1
    for (int h = 0; h < 8; h++) {
        float q[4], kk[4], vv[4];
#pragma unroll
        for (int d = 0; d < 4; d++) {
            const ulonglong2* wq = (const ulonglong2*)(sW + (d * 24 + h)      * 32);
            const ulonglong2* wk = (const ulonglong2*)(sW + (d * 24 + 8 + h)  * 32);
            const ulonglong2* wv = (const ulonglong2*)(sW + (d * 24 + 16 + h) * 32);
            u64 aq = 0, ak = 0, av = 0;
#pragma unroll
            for (int j = 0; j < 8; j++) {
                ulonglong2 ww;
                ww = wq[j]; aq = fma2(e2[2*j+1], ww.y, fma2(e2[2*j], ww.x, aq));
                ww = wk[j]; ak = fma2(e2[2*j+1], ww.y, fma2(e2[2*j], ww.x, ak));
                ww = wv[j]; av = fma2(e2[2*j+1], ww.y, fma2(e2[2*j], ww.x, av));
            }
            float a, b;
            unpack2(aq, a, b); q[d]  = (a + b) * 0.5f;
            unpack2(ak, a, b); kk[d] = a + b;
            unpack2(av, a, b); vv[d] = a + b;
        }
        *(float4*)(skv + lane * 12)     = make_float4(kk[0], kk[1], kk[2], kk[3]);
        *(float4*)(skv + lane * 12 + 4) = make_float4(vv[0], vv[1], vv[2], vv[3]);
        u64 q01 = pack2(q[0], q[1]), q23 = pack2(q[2], q[3]);
        __syncwarp();

        float sum = 0.f;
        u64 a01 = 0, a23 = 0;
#pragma unroll
        for (int s = 0; s < 32; s++) {
            ulonglong2 k2 = *(const ulonglong2*)(skv + s * 12);
            ulonglong2 v2 = *(const ulonglong2*)(skv + s * 12 + 4);
            u64 t = fma2(q23, k2.y, mul2(q01, k2.x));
            float ta, tb; unpack2(t, ta, tb);
            float p = __expf(ta + tb);
            sum += p;
            u64 p2 = pack2(p, p);
            a01 = fma2(p2, v2.x, a01);
            a23 = fma2(p2, v2.y, a23);
        }
        __syncwarp();
        float inv = 1.f / sum;
        float oa, ob, oc, od;
        unpack2(a01, oa, ob); unpack2(a23, oc, od);
        u64 o01 = pack2(oa * inv, ob * inv), o23 = pack2(oc * inv, od * inv);

        const float* w0h = sW0 + 4 * h;
#pragma unroll
        for (int j = 0; j < 32; j += 2) {
            ulonglong2 wa = *(const ulonglong2*)(w0h + j * 32);
            ulonglong2 wb = *(const ulonglong2*)(w0h + (j + 1) * 32);
            u64 ra = fma2(o23, wa.y, mul2(o01, wa.x));
            u64 rb = fma2(o23, wb.y, mul2(o01, wb.x));
            float xa, xb;
            unpack2(ra, xa, xb); rr[j]     += xa + xb;
            unpack2(rb, xa, xb); rr[j + 1] += xa + xb;
        }
    }

    float s1 = 0.f;
#pragma unroll
    for (int j = 0; j < 32; j++) s1 += rr[j];
    float mu = s1 * 0.03125f;
    float sq = 0.f;
#pragma unroll
    for (int j = 0; j < 32; j++) { float d = rr[j] - mu; sq = fmaf(d, d, sq); }
    float rstd = rsqrtf(sq * 0.03125f + 1e-5f);

    float* po = og + lane * 32;
#pragma unroll
    for (int j = 0; j < 32; j += 4) {
        float4 v;
        v.x = sigmoid_((rr[j]     - mu) * rstd * sgb[j]     + sgb[32 + j]);
        v.y = sigmoid_((rr[j + 1] - mu) * rstd * sgb[j + 1] + sgb[33 + j]);
        v.z = sigmoid_((rr[j + 2] - mu) * rstd * sgb[j + 2] + sgb[34 + j]);
        v.w = sigmoid_((rr[j + 3] - mu) * rstd * sgb[j + 3] + sgb[35 + j]);
        *(float4*)(po + j) = v;
    }
}

// ---------------------------------------------------------------------------
// K3 merged: blockIdx < nY -> R10's verified tensor-core y-path (residual out);
//            blockIdx >= nY -> verified x-path (gate out to g_sg2).
// ---------------------------------------------------------------------------
__global__ void __launch_bounds__(128) k_attn_all(
    const float* __restrict__ Wqvk, const float* __restrict__ W0,
    const float* __restrict__ Wqx, const float* __restrict__ W0x,
    const float* __restrict__ gx, const float* __restrict__ bx,
    int nY, int nb4)
{
    extern __shared__ float sm[];
    int tid = threadIdx.x;
    int w = tid >> 5, lane = tid & 31;

    if ((int)blockIdx.x >= nY) {
        // ================= x-branch path (verified k_attn_x2 body) =========
        float* sW  = sm;           // 3072
        float* sW0 = sm + 3072;    // 1024
        float* sgb = sm + 4096;    // 64
        float* tiles = sm + 4160;  // 4*384

        int xid = blockIdx.x - nY;
        int c  = xid / nb4;
        int bq = xid % nb4;

        for (int k = tid; k < 768; k += 128) ((float4*)sW)[k]  = ((const float4*)(Wqx + c * 3072))[k];
        for (int k = tid; k < 256; k += 128) ((float4*)sW0)[k] = ((const float4*)(W0x + c * 1024))[k];
        if (tid < 32) { sgb[tid] = gx[tid]; sgb[32 + tid] = bx[tid]; }
        __syncthreads();

        int bb = bq * 4 + w;
        const float* eg = g_emb + (((size_t)bb * 3 + 2) * 32 + 31) * 1024;
        float* og = g_sg2 + ((size_t)bb * 3 + c) * 1024;
        warp_attn_full(lane, eg, og, sW, sW0, sgb, tiles + w * 384);
        return;
    }

    // ================= y-branch path (R10's verified k_attn_y7 body) =======
    unsigned* sWt  = (unsigned*)sm;                 // 32*WS
    unsigned* sW0t = (unsigned*)sm + 32 * WS;       // 32*W0S

    const int WB = 32 * WS + 32 * W0S;              // weight words
    const int PW = 2 * 32 * ST + 32 * KVS;          // per-warp floats

    float* st   = sm + WB + w * PW;
    float* qbuf = st + 32 * ST;
    float* kvb  = qbuf + 32 * ST;
    unsigned* kvw = (unsigned*)kvb;

    int cid = blockIdx.x;
    int bc = cid >> 3;
    int ib = cid & 7;
    int c = bc % 3;

    // stage transposed tf32 weights (once per CTA)
    for (int k = tid; k < 3072; k += 128) {
        int f = k >> 5, j = k & 31;
        sWt[j * WS + f] = tf32_(Wqvk[c * 3072 + k]);
    }
    for (int k = tid; k < 1024; k += 128) {
        int jo = k >> 5, ji = k & 31;
        sW0t[ji * W0S + jo] = tf32_(W0[c * 1024 + k]);
    }
    __syncthreads();

    int i = ib * 4 + w;
    const float* eg = g_emb + ((size_t)bc * 32 + i) * 1024;
    float* og       = g_sig + ((size_t)bc * 32 + i) * 1024;

    int gid = lane >> 2;
    int tig = lane & 3;

    // ---- stage E coalesced -> stride-ST ----
#pragma unroll
    for (int r = 0; r < 32; r++) st[r * ST + lane] = eg[r * 32 + lane];
    __syncwarp();

    // ---- A fragments of E ----
    unsigned aq[2][4][4];
#pragma unroll
    for (int m = 0; m < 2; m++)
#pragma unroll
        for (int kk = 0; kk < 4; kk++) {
            int r = m * 16 + gid, cc = kk * 8 + tig;
            aq[m][kk][0] = tf32_(st[r * ST + cc]);
            aq[m][kk][1] = tf32_(st[(r + 8) * ST + cc]);
            aq[m][kk][2] = tf32_(st[r * ST + cc + 4]);
            aq[m][kk][3] = tf32_(st[(r + 8) * ST + cc + 4]);
        }

    const float QS = 0.72134752044f;   // 0.5 * log2(e)

    // ---- QKV GEMM, d-pair major; q -> qbuf, KV -> packed half2 words ----
#pragma unroll
    for (int dp = 0; dp < 2; dp++) {
        float cck[2][2][4], ccv[2][2][4];   // [dd][m][reg]
#pragma unroll
        for (int dd = 0; dd < 2; dd++) {
            int d = 2 * dp + dd;
#pragma unroll
            for (int wh = 0; wh < 3; wh++) {
                int n = 3 * d + wh;     // n-tile: f = d*24 + wh*8 + h
                unsigned b[4][2];
#pragma unroll
                for (int kk = 0; kk < 4; kk++) {
                    b[kk][0] = sWt[(kk * 8 + tig) * WS + n * 8 + gid];
                    b[kk][1] = sWt[(kk * 8 + tig + 4) * WS + n * 8 + gid];
                }
#pragma unroll
                for (int m = 0; m < 2; m++) {
                    float cc[4] = {0.f, 0.f, 0.f, 0.f};
#pragma unroll
                    for (int kk = 0; kk < 4; kk++) mma_(cc, aq[m][kk], b[kk]);
                    if (wh == 0) {
                        int t = m * 16 + gid, h = 2 * tig;
                        qbuf[t * ST + h * 4 + d]             = cc[0] * QS;
                        qbuf[t * ST + (h + 1) * 4 + d]       = cc[1] * QS;
                        qbuf[(t + 8) * ST + h * 4 + d]       = cc[2] * QS;
                        qbuf[(t + 8) * ST + (h + 1) * 4 + d] = cc[3] * QS;
                    } else if (wh == 1) {
#pragma unroll
                        for (int r2 = 0; r2 < 4; r2++) cck[dd][m][r2] = cc[r2];
                    } else {
#pragma unroll
                        for (int r2 = 0; r2 < 4; r2++) ccv[dd][m][r2] = cc[r2];
                    }
                }
            }
        }
        // pack (d, d+1) half2 and store words: kv slot (t,h) = [k01,k23,v01,v23]
#pragma unroll
        for (int m = 0; m < 2; m++)
#pragma unroll
            for (int rh = 0; rh < 2; rh++)
#pragma unroll
                for (int p = 0; p < 2; p++) {
                    int reg = p + 2 * rh;
                    int t = m * 16 + rh * 8 + gid;
                    int h = 2 * tig + p;
                    unsigned kw = h2u(__floats2half2_rn(cck[0][m][reg], cck[1][m][reg]));
                    unsigned vw = h2u(__floats2half2_rn(ccv[0][m][reg], ccv[1][m][reg]));
                    kvw[t * KVS + 4 * h + dp]     = kw;
                    kvw[t * KVS + 4 * h + 2 + dp] = vw;
                }
    }
    __syncwarp();

    // ---- per-head softmax(exp2) + AV; o overwrites q slot in qbuf ----
#pragma unroll 1
    for (int h = 0; h < 8; h++) {
        float q0 = qbuf[lane * ST + 4 * h + 0];
        float q1 = qbuf[lane * ST + 4 * h + 1];
        float q2 = qbuf[lane * ST + 4 * h + 2];
        float q3 = qbuf[lane * ST + 4 * h + 3];
        u64 q01 = pack2(q0, q1), q23 = pack2(q2, q3);

        float sum = 0.f;
        u64 a01 = 0, a23 = 0;
#pragma unroll 8
        for (int s = 0; s < 32; s++) {
            uint4 u = *(uint4*)(kvw + s * KVS + 4 * h);   // uniform broadcast
            u64 t = fma2(q23, f2u(u2f2(u.y)), mul2(q01, f2u(u2f2(u.x))));
            float ta, tb; unpack2(t, ta, tb);
            float p = ex2_(ta + tb);
            sum += p;
            u64 p2 = pack2(p, p);
            a01 = fma2(p2, f2u(u2f2(u.z)), a01);
            a23 = fma2(p2, f2u(u2f2(u.w)), a23);
        }
        float inv = 1.f / sum;
        float oa, ob, oc, od;
        unpack2(a01, oa, ob); unpack2(a23, oc, od);
        qbuf[lane * ST + 4 * h + 0] = oa * inv;
        qbuf[lane * ST + 4 * h + 1] = ob * inv;
        qbuf[lane * ST + 4 * h + 2] = oc * inv;
        qbuf[lane * ST + 4 * h + 3] = od * inv;
    }
    __syncwarp();   // o matrix complete before cross-lane fragment reads

    // ---- W0 GEMM + residual (in-place into st) ----
    unsigned ao[2][4][4];
#pragma unroll
    for (int m = 0; m < 2; m++)
#pragma unroll
        for (int kk = 0; kk < 4; kk++) {
            int r = m * 16 + gid, cc = kk * 8 + tig;
            ao[m][kk][0] = tf32_(qbuf[r * ST + cc]);
            ao[m][kk][1] = tf32_(qbuf[(r + 8) * ST + cc]);
            ao[m][kk][2] = tf32_(qbuf[r * ST + cc + 4]);
            ao[m][kk][3] = tf32_(qbuf[(r + 8) * ST + cc + 4]);
        }

#pragma unroll
    for (int n = 0; n < 4; n++) {
        unsigned b[4][2];
#pragma unroll
        for (int kk = 0; kk < 4; kk++) {
            b[kk][0] = sW0t[(kk * 8 + tig) * W0S + n * 8 + gid];
            b[kk][1] = sW0t[(kk * 8 + tig + 4) * W0S + n * 8 + gid];
        }
#pragma unroll
        for (int m = 0; m < 2; m++) {
            float cc[4] = {0.f, 0.f, 0.f, 0.f};
#pragma unroll
            for (int kk = 0; kk < 4; kk++) mma_(cc, ao[m][kk], b[kk]);
            int t = m * 16 + gid;
            int f0 = n * 8 + 2 * tig;
            st[t * ST + f0]           += cc[0];
            st[t * ST + f0 + 1]       += cc[1];
            st[(t + 8) * ST + f0]     += cc[2];
            st[(t + 8) * ST + f0 + 1] += cc[3];
        }
    }
    __syncwarp();

    // ---- coalesced store of residual ----
#pragma unroll
    for (int r = 0; r < 32; r++) og[r * 32 + lane] = st[r * ST + lane];
}

// ---------------------------------------------------------------------------
// K4 (R10 verified): gate_y = sigmoid(LN(res)); out = sg2 * gate_y * x.
// ---------------------------------------------------------------------------
__global__ void __launch_bounds__(256) k_final(const float* __restrict__ x,
                                               const float* __restrict__ gam,
                                               const float* __restrict__ bet,
                                               float* __restrict__ out)
{
    __shared__ float gs[32 * 33];
    __shared__ float ss[32];
    int bct = blockIdx.x;
    int t = bct & 31;
    int bc = bct >> 5;
    int tid = threadIdx.x;

    int i = tid >> 3, j0 = (tid & 7) * 4;
    size_t base = ((size_t)bc * 32 + i) * 1024 + t * 32 + j0;
    float4 v = *(const float4*)(g_sig + base);

    float s1 = v.x + v.y + v.z + v.w;
    float s2 = fmaf(v.x, v.x, fmaf(v.y, v.y, fmaf(v.z, v.z, v.w * v.w)));
#pragma unroll
    for (int m = 1; m < 8; m <<= 1) {
        s1 += __shfl_xor_sync(0xffffffffu, s1, m);
        s2 += __shfl_xor_sync(0xffffffffu, s2, m);
    }
    float mu = s1 * 0.03125f;
    float var = fmaf(-mu, mu, s2 * 0.03125f);
    float rstd = rsqrtf(var + 1e-5f);

    float4 gm = *(const float4*)(gam + j0);
    float4 bt = *(const float4*)(bet + j0);
    gs[i * 33 + j0 + 0] = sigmoid_((v.x - mu) * rstd * gm.x + bt.x);
    gs[i * 33 + j0 + 1] = sigmoid_((v.y - mu) * rstd * gm.y + bt.y);
    gs[i * 33 + j0 + 2] = sigmoid_((v.z - mu) * rstd * gm.z + bt.z);
    gs[i * 33 + j0 + 3] = sigmoid_((v.w - mu) * rstd * gm.w + bt.w);
    if (tid < 32) ss[tid] = g_sg2[(size_t)bc * 1024 + tid * 32 + t];
    __syncthreads();

    float4 xv = ((const float4*)(x + (size_t)bct * 1024))[tid];
    int jj = tid >> 3, i0 = (tid & 7) * 4;
    float4 ov;
    ov.x = ss[i0 + 0] * gs[(i0 + 0) * 33 + jj] * xv.x;
    ov.y = ss[i0 + 1] * gs[(i0 + 1) * 33 + jj] * xv.y;
    ov.z = ss[i0 + 2] * gs[(i0 + 2) * 33 + jj] * xv.z;
    ov.w = ss[i0 + 3] * gs[(i0 + 3) * 33 + jj] * xv.w;
    ((float4*)(out + (size_t)bct * 1024))[tid] = ov;
}

// ---------------------------------------------------------------------------
extern "C" void kernel_launch(void* const* d_in, const int* in_sizes, int n_in,
                              void* d_out, int out_size)
{
    const float* x   = (const float*)d_in[0];
    const float* pos = (const float*)d_in[1];
    const float* Wqy = (const float*)d_in[2];
    const float* W0y = (const float*)d_in[3];
    const float* gy  = (const float*)d_in[4];
    const float* by  = (const float*)d_in[5];
    const float* Wqx = (const float*)d_in[6];
    const float* W0x = (const float*)d_in[7];
    const float* gx  = (const float*)d_in[8];
    const float* bx  = (const float*)d_in[9];
    float* out = (float*)d_out;

    int B = in_sizes[0] / 98304;  // 3*32*32*32

    const int SMEM_Y = (32 * WS + 32 * W0S + 4 * (2 * 32 * ST + 32 * KVS)) * 4;  // 74,752 B
    cudaFuncSetAttribute(k_attn_all, cudaFuncAttributeMaxDynamicSharedMemorySize, SMEM_Y);

    int nY = B * 24;          // y CTAs (4 tiles each)
    int nb4 = B / 4;
    int nX = 3 * nb4;         // x CTAs

    k_emb2<<<B * 3, 256>>>(x, pos);
    k_attn_all<<<nY + nX, 128, SMEM_Y>>>(Wqy, W0y, Wqx, W0x, gx, bx, nY, nb4);
    k_final<<<B * 96, 256>>>(x, gy, by, out);
}

// round 17
// speedup vs baseline: 1.2762x; 1.1526x over previous
#include <cuda_runtime.h>
#include <cuda_fp16.h>

typedef unsigned long long u64;

#define B_MAX 256

__device__ float g_emb[B_MAX * 3 * 32 * 32 * 32];  // [b][c][i][t][j]
__device__ float g_sig[B_MAX * 3 * 32 * 32 * 32];  // y-branch residual (emb + proj)
__device__ float g_sg2[B_MAX * 3 * 32 * 32];       // sigmoid(LN(x-branch))

// ---------------- packed f32x2 + misc helpers ----------------
__device__ __forceinline__ u64 pack2(float lo, float hi) {
    u64 r; asm("mov.b64 %0, {%1, %2};" : "=l"(r) : "f"(lo), "f"(hi)); return r;
}
__device__ __forceinline__ void unpack2(u64 v, float& lo, float& hi) {
    asm("mov.b64 {%0, %1}, %2;" : "=f"(lo), "=f"(hi) : "l"(v));
}
__device__ __forceinline__ u64 fma2(u64 a, u64 b, u64 c) {
    u64 d; asm("fma.rn.f32x2 %0, %1, %2, %3;" : "=l"(d) : "l"(a), "l"(b), "l"(c)); return d;
}
__device__ __forceinline__ u64 mul2(u64 a, u64 b) {
    u64 d; asm("mul.rn.f32x2 %0, %1, %2;" : "=l"(d) : "l"(a), "l"(b)); return d;
}
__device__ __forceinline__ u64 f2u(float2 v) {
    u64 r; asm("mov.b64 %0, {%1, %2};" : "=l"(r) : "f"(v.x), "f"(v.y)); return r;
}
__device__ __forceinline__ unsigned h2u(__half2 h) { return *(unsigned*)&h; }
__device__ __forceinline__ float2 u2f2(unsigned u) { __half2 h = *(__half2*)&u; return __half22float2(h); }
__device__ __forceinline__ float ex2_(float x) {
    float r; asm("ex2.approx.f32 %0, %1;" : "=f"(r) : "f"(x)); return r;
}
__device__ __forceinline__ float sigmoid_(float v) { return 1.0f / (1.0f + __expf(-v)); }
__device__ __forceinline__ unsigned tf32_(float x) {
    unsigned u; asm("cvt.rna.tf32.f32 %0, %1;" : "=r"(u) : "f"(x)); return u;
}
__device__ __forceinline__ void mma_(float c[4], const unsigned a[4], const unsigned b[2]) {
    asm volatile(
        "mma.sync.aligned.m16n8k8.row.col.f32.tf32.tf32.f32 "
        "{%0,%1,%2,%3}, {%4,%5,%6,%7}, {%8,%9}, {%0,%1,%2,%3};"
        : "+f"(c[0]), "+f"(c[1]), "+f"(c[2]), "+f"(c[3])
        : "r"(a[0]), "r"(a[1]), "r"(a[2]), "r"(a[3]), "r"(b[0]), "r"(b[1]));
}

// bank-conflict-free strides (verified R10):
#define ST 37     // st/qbuf row stride
#define WS 104    // sWt row stride (8 mod 32)
#define W0S 40    // sW0t row stride (8 mod 32)
#define KVS 36    // kv token stride in 32-bit words
#define XS 40     // k_emb3 staging stride (8 mod 32 -> frag reads conflict-free)

// ---------------------------------------------------------------------------
// K1 v3: tensorized emb. Per (b,c): 32 GEMMs E_t[i][j] = sum_d x[t][d][i]*p[j][d].
// B(pos) fragments in registers once per CTA; warp-private staging; no CTA syncs.
// ---------------------------------------------------------------------------
__global__ void __launch_bounds__(256) k_emb3(const float* __restrict__ x,
                                              const float* __restrict__ pos)
{
    __shared__ float xsb[8][32 * XS];   // 40 KB, warp-private tiles

    int bc = blockIdx.x;
    int c = bc % 3;
    int tid = threadIdx.x;
    int w = tid >> 5, lane = tid & 31;
    int gid = lane >> 2, tig = lane & 3;
    float* xs = xsb[w];

    // B fragments: B[k=d][n=j] = pos[c][j][d]  (loaded once, reused for all t)
    unsigned bf[4][4][2];
    const float* pc = pos + c * 1024;
#pragma unroll
    for (int n = 0; n < 4; n++)
#pragma unroll
        for (int kk = 0; kk < 4; kk++) {
            bf[n][kk][0] = tf32_(pc[(n * 8 + gid) * 32 + kk * 8 + tig]);
            bf[n][kk][1] = tf32_(pc[(n * 8 + gid) * 32 + kk * 8 + tig + 4]);
        }

    const float* xb = x + (size_t)bc * 32768;
    float* ob = g_emb + (size_t)bc * 32768;

#pragma unroll 1
    for (int r8 = 0; r8 < 4; r8++) {
        int t = r8 * 8 + w;
        const float* xt = xb + (size_t)t * 1024;

        // ---- stage x[t] (d-major) into warp tile, stride XS ----
#pragma unroll
        for (int q = 0; q < 8; q++) {
            int f = lane + 32 * q;          // float4 index
            float4 v = ((const float4*)xt)[f];
            int d = f >> 3, i0 = (f & 7) * 4;
            xs[d * XS + i0 + 0] = v.x;
            xs[d * XS + i0 + 1] = v.y;
            xs[d * XS + i0 + 2] = v.z;
            xs[d * XS + i0 + 3] = v.w;
        }
        __syncwarp();

        // ---- A fragments: A[i][d] = xs[d*XS + i] (conflict-free) ----
        unsigned af[2][4][4];
#pragma unroll
        for (int m = 0; m < 2; m++)
#pragma unroll
            for (int kk = 0; kk < 4; kk++) {
                int r = m * 16 + gid, cc = kk * 8 + tig;
                af[m][kk][0] = tf32_(xs[cc * XS + r]);
                af[m][kk][1] = tf32_(xs[cc * XS + r + 8]);
                af[m][kk][2] = tf32_(xs[(cc + 4) * XS + r]);
                af[m][kk][3] = tf32_(xs[(cc + 4) * XS + r + 8]);
            }
        __syncwarp();   // frags in regs before next round's staging

        // ---- 32 MMAs + fragment-layout stores (8 full sectors/instr) ----
#pragma unroll
        for (int n = 0; n < 4; n++)
#pragma unroll
            for (int m = 0; m < 2; m++) {
                float cc4[4] = {0.f, 0.f, 0.f, 0.f};
#pragma unroll
                for (int kk = 0; kk < 4; kk++) mma_(cc4, af[m][kk], bf[n][kk]);
                float* dst = ob + (size_t)(m * 16 + gid) * 1024 + t * 32 + n * 8 + 2 * tig;
                *(float2*)dst = make_float2(cc4[0], cc4[1]);
                *(float2*)(dst + 8 * 1024) = make_float2(cc4[2], cc4[3]);
            }
    }
}

// ---------------------------------------------------------------------------
// x-branch full warp attention (verified, fp32)
// ---------------------------------------------------------------------------
__device__ __forceinline__ void warp_attn_full(
    int lane,
    const float* __restrict__ eg, float* __restrict__ og,
    const float* __restrict__ sW, const float* __restrict__ sW0,
    const float* __restrict__ sgb, float* __restrict__ skv)
{
    u64 e2[16];
    {
        const ulonglong2* ep = (const ulonglong2*)(eg + lane * 32);
#pragma unroll
        for (int j = 0; j < 8; j++) { ulonglong2 v = ep[j]; e2[2*j] = v.x; e2[2*j+1] = v.y; }
    }
    float rr[32];
#pragma unroll
    for (int j = 0; j < 16; j++) unpack2(e2[j], rr[2*j], rr[2*j+1]);

#pragma unroll 1
    for (int h = 0; h < 8; h++) {
        float q[4], kk[4], vv[4];
#pragma unroll
        for (int d = 0; d < 4; d++) {
            const ulonglong2* wq = (const ulonglong2*)(sW + (d * 24 + h)      * 32);
            const ulonglong2* wk = (const ulonglong2*)(sW + (d * 24 + 8 + h)  * 32);
            const ulonglong2* wv = (const ulonglong2*)(sW + (d * 24 + 16 + h) * 32);
            u64 aq = 0, ak = 0, av = 0;
#pragma unroll
            for (int j = 0; j < 8; j++) {
                ulonglong2 ww;
                ww = wq[j]; aq = fma2(e2[2*j+1], ww.y, fma2(e2[2*j], ww.x, aq));
                ww = wk[j]; ak = fma2(e2[2*j+1], ww.y, fma2(e2[2*j], ww.x, ak));
                ww = wv[j]; av = fma2(e2[2*j+1], ww.y, fma2(e2[2*j], ww.x, av));
            }
            float a, b;
            unpack2(aq, a, b); q[d]  = (a + b) * 0.5f;
            unpack2(ak, a, b); kk[d] = a + b;
            unpack2(av, a, b); vv[d] = a + b;
        }
        *(float4*)(skv + lane * 12)     = make_float4(kk[0], kk[1], kk[2], kk[3]);
        *(float4*)(skv + lane * 12 + 4) = make_float4(vv[0], vv[1], vv[2], vv[3]);
        u64 q01 = pack2(q[0], q[1]), q23 = pack2(q[2], q[3]);
        __syncwarp();

        float sum = 0.f;
        u64 a01 = 0, a23 = 0;
#pragma unroll
        for (int s = 0; s < 32; s++) {
            ulonglong2 k2 = *(const ulonglong2*)(skv + s * 12);
            ulonglong2 v2 = *(const ulonglong2*)(skv + s * 12 + 4);
            u64 t = fma2(q23, k2.y, mul2(q01, k2.x));
            float ta, tb; unpack2(t, ta, tb);
            float p = __expf(ta + tb);
            sum += p;
            u64 p2 = pack2(p, p);
            a01 = fma2(p2, v2.x, a01);
            a23 = fma2(p2, v2.y, a23);
        }
        __syncwarp();
        float inv = 1.f / sum;
        float oa, ob, oc, od;
        unpack2(a01, oa, ob); unpack2(a23, oc, od);
        u64 o01 = pack2(oa * inv, ob * inv), o23 = pack2(oc * inv, od * inv);

        const float* w0h = sW0 + 4 * h;
#pragma unroll
        for (int j = 0; j < 32; j += 2) {
            ulonglong2 wa = *(const ulonglong2*)(w0h + j * 32);
            ulonglong2 wb = *(const ulonglong2*)(w0h + (j + 1) * 32);
            u64 ra = fma2(o23, wa.y, mul2(o01, wa.x));
            u64 rb = fma2(o23, wb.y, mul2(o01, wb.x));
            float xa, xb;
            unpack2(ra, xa, xb); rr[j]     += xa + xb;
            unpack2(rb, xa, xb); rr[j + 1] += xa + xb;
        }
    }

    float s1 = 0.f;
#pragma unroll
    for (int j = 0; j < 32; j++) s1 += rr[j];
    float mu = s1 * 0.03125f;
    float sq = 0.f;
#pragma unroll
    for (int j = 0; j < 32; j++) { float d = rr[j] - mu; sq = fmaf(d, d, sq); }
    float rstd = rsqrtf(sq * 0.03125f + 1e-5f);

    float* po = og + lane * 32;
#pragma unroll
    for (int j = 0; j < 32; j += 4) {
        float4 v;
        v.x = sigmoid_((rr[j]     - mu) * rstd * sgb[j]     + sgb[32 + j]);
        v.y = sigmoid_((rr[j + 1] - mu) * rstd * sgb[j + 1] + sgb[33 + j]);
        v.z = sigmoid_((rr[j + 2] - mu) * rstd * sgb[j + 2] + sgb[34 + j]);
        v.w = sigmoid_((rr[j + 3] - mu) * rstd * sgb[j + 3] + sgb[35 + j]);
        *(float4*)(po + j) = v;
    }
}

// ---------------------------------------------------------------------------
// K3 merged (verified R16): y-path (tensor-core, residual out) + x-path.
// ---------------------------------------------------------------------------
__global__ void __launch_bounds__(128) k_attn_all(
    const float* __restrict__ Wqvk, const float* __restrict__ W0,
    const float* __restrict__ Wqx, const float* __restrict__ W0x,
    const float* __restrict__ gx, const float* __restrict__ bx,
    int nY, int nb4)
{
    extern __shared__ float sm[];
    int tid = threadIdx.x;
    int w = tid >> 5, lane = tid & 31;

    if ((int)blockIdx.x >= nY) {
        float* sW  = sm;
        float* sW0 = sm + 3072;
        float* sgb = sm + 4096;
        float* tiles = sm + 4160;

        int xid = blockIdx.x - nY;
        int c  = xid / nb4;
        int bq = xid % nb4;

        for (int k = tid; k < 768; k += 128) ((float4*)sW)[k]  = ((const float4*)(Wqx + c * 3072))[k];
        for (int k = tid; k < 256; k += 128) ((float4*)sW0)[k] = ((const float4*)(W0x + c * 1024))[k];
        if (tid < 32) { sgb[tid] = gx[tid]; sgb[32 + tid] = bx[tid]; }
        __syncthreads();

        int bb = bq * 4 + w;
        const float* eg = g_emb + (((size_t)bb * 3 + 2) * 32 + 31) * 1024;
        float* og = g_sg2 + ((size_t)bb * 3 + c) * 1024;
        warp_attn_full(lane, eg, og, sW, sW0, sgb, tiles + w * 384);
        return;
    }

    unsigned* sWt  = (unsigned*)sm;
    unsigned* sW0t = (unsigned*)sm + 32 * WS;

    const int WB = 32 * WS + 32 * W0S;
    const int PW = 2 * 32 * ST + 32 * KVS;

    float* st   = sm + WB + w * PW;
    float* qbuf = st + 32 * ST;
    float* kvb  = qbuf + 32 * ST;
    unsigned* kvw = (unsigned*)kvb;

    int cid = blockIdx.x;
    int bc = cid >> 3;
    int ib = cid & 7;
    int c = bc % 3;

    for (int k = tid; k < 3072; k += 128) {
        int f = k >> 5, j = k & 31;
        sWt[j * WS + f] = tf32_(Wqvk[c * 3072 + k]);
    }
    for (int k = tid; k < 1024; k += 128) {
        int jo = k >> 5, ji = k & 31;
        sW0t[ji * W0S + jo] = tf32_(W0[c * 1024 + k]);
    }
    __syncthreads();

    int i = ib * 4 + w;
    const float* eg = g_emb + ((size_t)bc * 32 + i) * 1024;
    float* og       = g_sig + ((size_t)bc * 32 + i) * 1024;

    int gid = lane >> 2;
    int tig = lane & 3;

#pragma unroll
    for (int r = 0; r < 32; r++) st[r * ST + lane] = eg[r * 32 + lane];
    __syncwarp();

    unsigned aq[2][4][4];
#pragma unroll
    for (int m = 0; m < 2; m++)
#pragma unroll
        for (int kk = 0; kk < 4; kk++) {
            int r = m * 16 + gid, cc = kk * 8 + tig;
            aq[m][kk][0] = tf32_(st[r * ST + cc]);
            aq[m][kk][1] = tf32_(st[(r + 8) * ST + cc]);
            aq[m][kk][2] = tf32_(st[r * ST + cc + 4]);
            aq[m][kk][3] = tf32_(st[(r + 8) * ST + cc + 4]);
        }

    const float QS = 0.72134752044f;   // 0.5 * log2(e)

#pragma unroll
    for (int dp = 0; dp < 2; dp++) {
        float cck[2][2][4], ccv[2][2][4];
#pragma unroll
        for (int dd = 0; dd < 2; dd++) {
            int d = 2 * dp + dd;
#pragma unroll
            for (int wh = 0; wh < 3; wh++) {
                int n = 3 * d + wh;
                unsigned b[4][2];
#pragma unroll
                for (int kk = 0; kk < 4; kk++) {
                    b[kk][0] = sWt[(kk * 8 + tig) * WS + n * 8 + gid];
                    b[kk][1] = sWt[(kk * 8 + tig + 4) * WS + n * 8 + gid];
                }
#pragma unroll
                for (int m = 0; m < 2; m++) {
                    float cc[4] = {0.f, 0.f, 0.f, 0.f};
#pragma unroll
                    for (int kk = 0; kk < 4; kk++) mma_(cc, aq[m][kk], b[kk]);
                    if (wh == 0) {
                        int t = m * 16 + gid, h = 2 * tig;
                        qbuf[t * ST + h * 4 + d]             = cc[0] * QS;
                        qbuf[t * ST + (h + 1) * 4 + d]       = cc[1] * QS;
                        qbuf[(t + 8) * ST + h * 4 + d]       = cc[2] * QS;
                        qbuf[(t + 8) * ST + (h + 1) * 4 + d] = cc[3] * QS;
                    } else if (wh == 1) {
#pragma unroll
                        for (int r2 = 0; r2 < 4; r2++) cck[dd][m][r2] = cc[r2];
                    } else {
#pragma unroll
                        for (int r2 = 0; r2 < 4; r2++) ccv[dd][m][r2] = cc[r2];
                    }
                }
            }
        }
#pragma unroll
        for (int m = 0; m < 2; m++)
#pragma unroll
            for (int rh = 0; rh < 2; rh++)
#pragma unroll
                for (int p = 0; p < 2; p++) {
                    int reg = p + 2 * rh;
                    int t = m * 16 + rh * 8 + gid;
                    int h = 2 * tig + p;
                    unsigned kw = h2u(__floats2half2_rn(cck[0][m][reg], cck[1][m][reg]));
                    unsigned vw = h2u(__floats2half2_rn(ccv[0][m][reg], ccv[1][m][reg]));
                    kvw[t * KVS + 4 * h + dp]     = kw;
                    kvw[t * KVS + 4 * h + 2 + dp] = vw;
                }
    }
    __syncwarp();

#pragma unroll 1
    for (int h = 0; h < 8; h++) {
        float q0 = qbuf[lane * ST + 4 * h + 0];
        float q1 = qbuf[lane * ST + 4 * h + 1];
        float q2 = qbuf[lane * ST + 4 * h + 2];
        float q3 = qbuf[lane * ST + 4 * h + 3];
        u64 q01 = pack2(q0, q1), q23 = pack2(q2, q3);

        float sum = 0.f;
        u64 a01 = 0, a23 = 0;
#pragma unroll 8
        for (int s = 0; s < 32; s++) {
            uint4 u = *(uint4*)(kvw + s * KVS + 4 * h);
            u64 t = fma2(q23, f2u(u2f2(u.y)), mul2(q01, f2u(u2f2(u.x))));
            float ta, tb; unpack2(t, ta, tb);
            float p = ex2_(ta + tb);
            sum += p;
            u64 p2 = pack2(p, p);
            a01 = fma2(p2, f2u(u2f2(u.z)), a01);
            a23 = fma2(p2, f2u(u2f2(u.w)), a23);
        }
        float inv = 1.f / sum;
        float oa, ob, oc, od;
        unpack2(a01, oa, ob); unpack2(a23, oc, od);
        qbuf[lane * ST + 4 * h + 0] = oa * inv;
        qbuf[lane * ST + 4 * h + 1] = ob * inv;
        qbuf[lane * ST + 4 * h + 2] = oc * inv;
        qbuf[lane * ST + 4 * h + 3] = od * inv;
    }
    __syncwarp();

    unsigned ao[2][4][4];
#pragma unroll
    for (int m = 0; m < 2; m++)
#pragma unroll
        for (int kk = 0; kk < 4; kk++) {
            int r = m * 16 + gid, cc = kk * 8 + tig;
            ao[m][kk][0] = tf32_(qbuf[r * ST + cc]);
            ao[m][kk][1] = tf32_(qbuf[(r + 8) * ST + cc]);
            ao[m][kk][2] = tf32_(qbuf[r * ST + cc + 4]);
            ao[m][kk][3] = tf32_(qbuf[(r + 8) * ST + cc + 4]);
        }

#pragma unroll
    for (int n = 0; n < 4; n++) {
        unsigned b[4][2];
#pragma unroll
        for (int kk = 0; kk < 4; kk++) {
            b[kk][0] = sW0t[(kk * 8 + tig) * W0S + n * 8 + gid];
            b[kk][1] = sW0t[(kk * 8 + tig + 4) * W0S + n * 8 + gid];
        }
#pragma unroll
        for (int m = 0; m < 2; m++) {
            float cc[4] = {0.f, 0.f, 0.f, 0.f};
#pragma unroll
            for (int kk = 0; kk < 4; kk++) mma_(cc, ao[m][kk], b[kk]);
            int t = m * 16 + gid;
            int f0 = n * 8 + 2 * tig;
            st[t * ST + f0]           += cc[0];
            st[t * ST + f0 + 1]       += cc[1];
            st[(t + 8) * ST + f0]     += cc[2];
            st[(t + 8) * ST + f0 + 1] += cc[3];
        }
    }
    __syncwarp();

#pragma unroll
    for (int r = 0; r < 32; r++) og[r * 32 + lane] = st[r * ST + lane];
}

// ---------------------------------------------------------------------------
// K4 (verified): gate_y = sigmoid(LN(res)); out = sg2 * gate_y * x.
// ---------------------------------------------------------------------------
__global__ void __launch_bounds__(256) k_final(const float* __restrict__ x,
                                               const float* __restrict__ gam,
                                               const float* __restrict__ bet,
                                               float* __restrict__ out)
{
    __shared__ float gs[32 * 33];
    __shared__ float ss[32];
    int bct = blockIdx.x;
    int t = bct & 31;
    int bc = bct >> 5;
    int tid = threadIdx.x;

    int i = tid >> 3, j0 = (tid & 7) * 4;
    size_t base = ((size_t)bc * 32 + i) * 1024 + t * 32 + j0;
    float4 v = *(const float4*)(g_sig + base);

    float s1 = v.x + v.y + v.z + v.w;
    float s2 = fmaf(v.x, v.x, fmaf(v.y, v.y, fmaf(v.z, v.z, v.w * v.w)));
#pragma unroll
    for (int m = 1; m < 8; m <<= 1) {
        s1 += __shfl_xor_sync(0xffffffffu, s1, m);
        s2 += __shfl_xor_sync(0xffffffffu, s2, m);
    }
    float mu = s1 * 0.03125f;
    float var = fmaf(-mu, mu, s2 * 0.03125f);
    float rstd = rsqrtf(var + 1e-5f);

    float4 gm = *(const float4*)(gam + j0);
    float4 bt = *(const float4*)(bet + j0);
    gs[i * 33 + j0 + 0] = sigmoid_((v.x - mu) * rstd * gm.x + bt.x);
    gs[i * 33 + j0 + 1] = sigmoid_((v.y - mu) * rstd * gm.y + bt.y);
    gs[i * 33 + j0 + 2] = sigmoid_((v.z - mu) * rstd * gm.z + bt.z);
    gs[i * 33 + j0 + 3] = sigmoid_((v.w - mu) * rstd * gm.w + bt.w);
    if (tid < 32) ss[tid] = g_sg2[(size_t)bc * 1024 + tid * 32 + t];
    __syncthreads();

    float4 xv = ((const float4*)(x + (size_t)bct * 1024))[tid];
    int jj = tid >> 3, i0 = (tid & 7) * 4;
    float4 ov;
    ov.x = ss[i0 + 0] * gs[(i0 + 0) * 33 + jj] * xv.x;
    ov.y = ss[i0 + 1] * gs[(i0 + 1) * 33 + jj] * xv.y;
    ov.z = ss[i0 + 2] * gs[(i0 + 2) * 33 + jj] * xv.z;
    ov.w = ss[i0 + 3] * gs[(i0 + 3) * 33 + jj] * xv.w;
    ((float4*)(out + (size_t)bct * 1024))[tid] = ov;
}

// ---------------------------------------------------------------------------
extern "C" void kernel_launch(void* const* d_in, const int* in_sizes, int n_in,
                              void* d_out, int out_size)
{
    const float* x   = (const float*)d_in[0];
    const float* pos = (const float*)d_in[1];
    const float* Wqy = (const float*)d_in[2];
    const float* W0y = (const float*)d_in[3];
    const float* gy  = (const float*)d_in[4];
    const float* by  = (const float*)d_in[5];
    const float* Wqx = (const float*)d_in[6];
    const float* W0x = (const float*)d_in[7];
    const float* gx  = (const float*)d_in[8];
    const float* bx  = (const float*)d_in[9];
    float* out = (float*)d_out;

    int B = in_sizes[0] / 98304;  // 3*32*32*32

    const int SMEM_Y = (32 * WS + 32 * W0S + 4 * (2 * 32 * ST + 32 * KVS)) * 4;  // 74,752 B
    cudaFuncSetAttribute(k_attn_all, cudaFuncAttributeMaxDynamicSharedMemorySize, SMEM_Y);

    int nY = B * 24;
    int nb4 = B / 4;
    int nX = 3 * nb4;

    k_emb3<<<B * 3, 256>>>(x, pos);
    k_attn_all<<<nY + nX, 128, SMEM_Y>>>(Wqy, W0y, Wqx, W0x, gx, bx, nY, nb4);
    k_final<<<B * 96, 256>>>(x, gy, by, out);
}